// round 15
// baseline (speedup 1.0000x reference)
#include <cuda_runtime.h>
#include <stdint.h>

// SpikeFP32Embedding: out[t, :, :] = weight_pulse[token_ids[t], :, :]
// token_ids: [16384] int32; weight_pulse: [32768, 128, 32] f32; out: [16384, 128, 32] f32
// Row = 16 KB = 512 x 32B chunks.
//
// Width A/B (de-conflating R4): 256-bit loads (ld.global.nc.v8.b32) with
// DEFAULT L2 policy — R4 tested 32B loads only together with evict_last.
// Halves LDG count and L1tex wavefront-queue entries vs 4x float4.
// Stores remain 4x __stcs float4 (no 256-bit store on sm_103a).

static constexpr int ROW_BYTES = 16384;
static constexpr int THREADS   = 256;
// Each thread: 2 chunks of 32B -> 64B; 256 thr * 64B = 16KB. chunk stride 8192B.

struct Chunk32 { float4 a, b; };

__device__ __forceinline__ Chunk32 ldg256(const void* p)
{
    Chunk32 c;
    asm volatile("ld.global.nc.v8.b32 {%0,%1,%2,%3,%4,%5,%6,%7}, [%8];"
                 : "=f"(c.a.x), "=f"(c.a.y), "=f"(c.a.z), "=f"(c.a.w),
                   "=f"(c.b.x), "=f"(c.b.y), "=f"(c.b.z), "=f"(c.b.w)
                 : "l"(p));
    return c;
}

__global__ __launch_bounds__(THREADS, 8)
void spike_embed_gather(const int* __restrict__ tok,
                        const char* __restrict__ pulse,
                        char* __restrict__ out)
{
    const int t = blockIdx.x;
    const int row = __ldg(tok + t);

    const char* __restrict__ src = pulse + (size_t)row * ROW_BYTES + threadIdx.x * 32;
    char* __restrict__ dst = out + (size_t)t * ROW_BYTES + threadIdx.x * 32;

    // 2 x 32B loads, batched (MLP_p1 = 2 LDG.256 = 2 wavefront entries)
    Chunk32 v0 = ldg256(src);
    Chunk32 v1 = ldg256(src + THREADS * 32);

    float4* d0 = reinterpret_cast<float4*>(dst);
    float4* d1 = reinterpret_cast<float4*>(dst + THREADS * 32);
    __stcs(d0 + 0, v0.a);
    __stcs(d0 + 1, v0.b);
    __stcs(d1 + 0, v1.a);
    __stcs(d1 + 1, v1.b);
}

extern "C" void kernel_launch(void* const* d_in, const int* in_sizes, int n_in,
                              void* d_out, int out_size)
{
    const int*  tok   = (const int*)d_in[0];     // [16384]
    const char* pulse = (const char*)d_in[1];    // [32768 * 16384] bytes
    char*       out   = (char*)d_out;

    const int n_tokens = in_sizes[0];            // 16384
    spike_embed_gather<<<n_tokens, THREADS>>>(tok, pulse, out);
}

// round 16
// speedup vs baseline: 1.0118x; 1.0118x over previous
#include <cuda_runtime.h>
#include <stdint.h>

// SpikeFP32Embedding: out[t, :, :] = weight_pulse[token_ids[t], :, :]
// token_ids: [8*2048] int32; weight_pulse: [32768, 128, 32] f32; out: [16384, 128, 32] f32
// Row = 128*32 floats = 4096 f32 = 1024 float4 = 16 KB.
//
// FINAL (converged, 15 rounds). One CTA per token, 256 threads, 4x 128-bit
// loads batched then 4x streaming stores. Moves the traffic floor (~203MB
// unique-row reads + 256MB mandatory writes = 459MB) at ~6.15 TB/s — the
// measured GB300 effective DRAM ceiling for this 56/44 read/write mix.
//
// Complete experiment log (kernel time vs this 74.75us baseline):
//   counting-sort token dedup      +35us overhead; duplicates already L2-hit
//   L2::evict_last + 32B loads     78.4us
//   32B loads, default policy      79.5us  -> width (not policy) costs ~5%:
//                                             L2 busy jumps 38%->55% at 32B
//   default write-back stores      75.0us  (neutral vs __stcs)
//   persistent pipelined CTAs      78.0us  (occupancy/serialization)
//   TMA bulk-copy smem ring        79.1us  (path-equivalent at LTS cap)
//   2 tokens per CTA               75.5us  (neutral)
//   128 thr x 8 float4 (MLP8)      77.3us  (L1tex wavefront-queue contention)
//   512 thr x 2 float4 (MLP2)      75.7us  (insufficient per-warp MLP)
//   256 thr x 4 float4 (MLP4)      74.75us <- optimum on every axis

static constexpr int ROW_FLOAT4 = 1024;   // float4 per row
static constexpr int THREADS    = 256;
static constexpr int PER_THREAD = ROW_FLOAT4 / THREADS;  // 4

__global__ __launch_bounds__(THREADS, 8)
void spike_embed_gather(const int* __restrict__ tok,
                        const float4* __restrict__ pulse,
                        float4* __restrict__ out)
{
    const int t = blockIdx.x;
    const int row = __ldg(tok + t);

    const float4* __restrict__ src = pulse + (size_t)row * ROW_FLOAT4 + threadIdx.x;
    float4* __restrict__ dst = out + (size_t)t * ROW_FLOAT4 + threadIdx.x;

    float4 v[PER_THREAD];
#pragma unroll
    for (int i = 0; i < PER_THREAD; ++i)
        v[i] = __ldg(src + i * THREADS);

#pragma unroll
    for (int i = 0; i < PER_THREAD; ++i)
        __stcs(dst + i * THREADS, v[i]);
}

extern "C" void kernel_launch(void* const* d_in, const int* in_sizes, int n_in,
                              void* d_out, int out_size)
{
    const int*    tok   = (const int*)d_in[0];       // [16384]
    const float4* pulse = (const float4*)d_in[1];    // [32768*1024] float4
    float4*       out   = (float4*)d_out;

    const int n_tokens = in_sizes[0];                // 16384
    spike_embed_gather<<<n_tokens, THREADS>>>(tok, pulse, out);
}

// round 17
// speedup vs baseline: 1.0186x; 1.0067x over previous
#include <cuda_runtime.h>
#include <stdint.h>

// SpikeFP32Embedding: out[t, :, :] = weight_pulse[token_ids[t], :, :]
// token_ids: [8*2048] int32; weight_pulse: [32768, 128, 32] f32; out: [16384, 128, 32] f32
// Row = 128*32 floats = 4096 f32 = 1024 float4 = 16 KB.
//
// FINAL (converged, 16 rounds). One CTA per token, 256 threads, 4x 128-bit
// loads batched then 4x streaming stores. Moves the traffic floor (~203MB
// unique-row reads + 256MB mandatory writes = 459MB) at ~6.1-6.15 TB/s — the
// measured GB300 effective DRAM ceiling for this 56/44 read/write mix.
//
// Complete experiment log (kernel time vs this 74.75-76.0us baseline):
//   counting-sort token dedup      +35us overhead; duplicates already L2-hit
//   L2::evict_last + 32B loads     78.4us
//   32B loads, default policy      79.5us  (width costs ~5%: L2 busy 38->55%)
//   default write-back stores      75.0us  (neutral vs __stcs)
//   persistent pipelined CTAs      78.0us  (occupancy/serialization)
//   TMA bulk-copy smem ring        79.1us  (path-equivalent at LTS cap)
//   2 tokens per CTA               75.5us  (neutral)
//   128 thr x 8 float4 (MLP8)      77.3us  (L1tex wavefront-queue contention)
//   512 thr x 2 float4 (MLP2)      75.7us  (insufficient per-warp MLP)
//   256 thr x 4 float4 (MLP4)      74.75us <- optimum on every axis

static constexpr int ROW_FLOAT4 = 1024;   // float4 per row
static constexpr int THREADS    = 256;
static constexpr int PER_THREAD = ROW_FLOAT4 / THREADS;  // 4

__global__ __launch_bounds__(THREADS, 8)
void spike_embed_gather(const int* __restrict__ tok,
                        const float4* __restrict__ pulse,
                        float4* __restrict__ out)
{
    const int t = blockIdx.x;
    const int row = __ldg(tok + t);

    const float4* __restrict__ src = pulse + (size_t)row * ROW_FLOAT4 + threadIdx.x;
    float4* __restrict__ dst = out + (size_t)t * ROW_FLOAT4 + threadIdx.x;

    float4 v[PER_THREAD];
#pragma unroll
    for (int i = 0; i < PER_THREAD; ++i)
        v[i] = __ldg(src + i * THREADS);

#pragma unroll
    for (int i = 0; i < PER_THREAD; ++i)
        __stcs(dst + i * THREADS, v[i]);
}

extern "C" void kernel_launch(void* const* d_in, const int* in_sizes, int n_in,
                              void* d_out, int out_size)
{
    const int*    tok   = (const int*)d_in[0];       // [16384]
    const float4* pulse = (const float4*)d_in[1];    // [32768*1024] float4
    float4*       out   = (float4*)d_out;

    const int n_tokens = in_sizes[0];                // 16384
    spike_embed_gather<<<n_tokens, THREADS>>>(tok, pulse, out);
}